// round 3
// baseline (speedup 1.0000x reference)
#include <cuda_runtime.h>

#define BSZ 128
#define HHOR 8
#define TSEQ 372
#define HID 1024
#define G4 4096
#define NCTA 128
#define TPB 256
#define JC 8
#define GD 32
#define NCH 33
#define SMEMB 209664

__device__ float    g_h[2][HID * BSZ];
__device__ float    g_bias[G4 * BSZ];     // [r][b]
__device__ float    g_temb[HID * BSZ];    // [h][b]
__device__ float    g_hm[512 * BSZ];      // [u][b]
__device__ float    g_xT[TSEQ * 64 * BSZ];
__device__ float    g_part[NCTA * HHOR * BSZ];
__device__ unsigned g_cnt;

typedef unsigned long long ull;

__device__ __forceinline__ float sigm(float x) { return 1.f / (1.f + expf(-x)); }

__device__ __forceinline__ ull pk2(float v) {
    ull r; asm("mov.b64 %0, {%1, %1};" : "=l"(r) : "f"(v)); return r;
}
__device__ __forceinline__ ull f2fma(ull a, ull b, ull c) {
    ull d; asm("fma.rn.f32x2 %0, %1, %2, %3;" : "=l"(d) : "l"(a), "l"(b), "l"(c)); return d;
}
__device__ __forceinline__ void upk(ull v, float& lo, float& hi) {
    asm("mov.b64 {%0, %1}, %2;" : "=f"(lo), "=f"(hi) : "l"(v));
}

// ---------------- setup ----------------
__global__ void s_emb_hm(const float* __restrict__ tval, const float* __restrict__ freqs,
                         const float* __restrict__ phases, const float* __restrict__ W1,
                         const float* __restrict__ b1)
{
    __shared__ float emb[256];
    const int b = blockIdx.x, tid = threadIdx.x;
    const float tv = tval[b];
    emb[tid] = cosf(fmaf(tv, freqs[tid], phases[tid])) * 1.41421356237309515f;
    __syncthreads();
    const float4* e4 = (const float4*)emb;
    for (int u = tid; u < 512; u += 256) {
        const float4* w4 = (const float4*)(W1 + u * 256);
        float s = b1[u];
        #pragma unroll 8
        for (int q = 0; q < 64; ++q) {
            float4 w = w4[q], e = e4[q];
            s += w.x * e.x + w.y * e.y + w.z * e.z + w.w * e.w;
        }
        g_hm[u * BSZ + b] = s * sigm(s);
    }
}

__global__ void s_temb(const float* __restrict__ W2, const float* __restrict__ b2)
{
    __shared__ float sW2[8 * 512];
    const int blk = blockIdx.x, tid = threadIdx.x;
    const int h0 = blk * 8;
    for (int idx = tid; idx < 4096; idx += 128) sW2[idx] = W2[h0 * 512 + idx];
    __syncthreads();
    const int b = tid;
    float acc[8];
    #pragma unroll
    for (int r = 0; r < 8; ++r) acc[r] = b2[h0 + r];
    #pragma unroll 8
    for (int u = 0; u < 512; ++u) {
        const float hmv = g_hm[u * BSZ + b];
        #pragma unroll
        for (int r = 0; r < 8; ++r) acc[r] = fmaf(sW2[r * 512 + u], hmv, acc[r]);
    }
    #pragma unroll
    for (int r = 0; r < 8; ++r) g_temb[(h0 + r) * BSZ + b] = acc[r];
}

__global__ void s_bias(const float* __restrict__ static_attr, const float* __restrict__ W_ih,
                       const float* __restrict__ b_ih, const float* __restrict__ b_hh)
{
    __shared__ float sst[27 * 128];
    __shared__ float sw[128 * 27];
    const int blk = blockIdx.x, tid = threadIdx.x;
    const int r0 = blk * 128;
    for (int idx = tid; idx < 27 * 128; idx += 256) {
        const int k = idx >> 7, b = idx & 127;
        sst[idx] = static_attr[b * 27 + k];
    }
    for (int idx = tid; idx < 128 * 27; idx += 256) {
        const int rl = idx / 27, k = idx - rl * 27;
        sw[idx] = W_ih[(r0 + rl) * 60 + 33 + k];
    }
    __syncthreads();
    for (int o = tid; o < 128 * 128; o += 256) {
        const int rl = o >> 7, b = o & 127;
        const int r = r0 + rl;
        float s = b_ih[r] + b_hh[r];
        #pragma unroll
        for (int k = 0; k < 27; ++k) s = fmaf(sw[rl * 27 + k], sst[k * 128 + b], s);
        g_bias[r * BSZ + b] = s;
    }
    for (int i = tid; i < 4096; i += 256) g_h[0][blk * 4096 + i] = 0.f;
    if (blk == 0 && tid == 0) g_cnt = 0u;
}

__global__ void s_xT(const float* __restrict__ x_past, const float* __restrict__ x_future,
                     const float* __restrict__ noisy)
{
    __shared__ float sx[33 * 128];
    const int t = blockIdx.x, b = threadIdx.x;
    const float* src = (t < 365) ? (x_past + (b * 365 + t) * 32)
                                 : (x_future + (b * 7 + (t - 365)) * 32);
    const float4* s4 = (const float4*)src;
    #pragma unroll
    for (int q = 0; q < 8; ++q) {
        float4 v = s4[q];
        sx[(q * 4 + 0) * 128 + b] = v.x;
        sx[(q * 4 + 1) * 128 + b] = v.y;
        sx[(q * 4 + 2) * 128 + b] = v.z;
        sx[(q * 4 + 3) * 128 + b] = v.w;
    }
    sx[32 * 128 + b] = (t >= 364) ? noisy[b * 8 + (t - 364)] : 0.f;
    __syncthreads();
    for (int idx = b; idx < 33 * 128; idx += 128)
        g_xT[t * 64 * BSZ + idx] = sx[idx];
}

// ---------------- main LSTM ----------------
__global__ void __launch_bounds__(TPB, 1)
lstm_main(const float* __restrict__ W_hh, const float* __restrict__ W_ih,
          const float* __restrict__ Wh)
{
    extern __shared__ float sm[];
    float* Wt     = sm;                    // [1057][32]
    float* Hs     = Wt + 1057 * 32;        // [2][32*128]
    float* bias_s = Hs + 8192;             // [32][128]
    float* temb_s = bias_s + 4096;         // [8][128]
    float* red    = temb_s + 1024;         // [128][33]
    float* red2   = red + 128 * 33;        // [8][132]

    const int tid = threadIdx.x;
    const int kz  = tid >> 7;
    const int gdt = (tid >> 4) & 7;
    const int bt  = tid & 15;
    const int b0  = bt * 8;
    const int b0k = b0 + kz * 4;
    const int cta = blockIdx.x;
    const int j0  = cta * JC;

    for (int idx = tid; idx < GD * 1057; idx += TPB) {
        const int gd = idx / 1057, k = idx - gd * 1057;
        const int jloc = gd >> 2, gate = gd & 3;
        const int r = gate * HID + j0 + jloc;
        float v;
        if (k < 1024)       v = W_hh[r * HID + k];
        else if (k < 1056)  v = W_ih[r * 60 + (k - 1024)];
        else                v = W_ih[r * 60 + 32];
        Wt[k * GD + gd] = v;
    }
    for (int idx = tid; idx < GD * BSZ; idx += TPB) {
        const int gd = idx >> 7, b = idx & 127;
        const int jloc = gd >> 2, gate = gd & 3;
        bias_s[gd * BSZ + b] = g_bias[(gate * HID + j0 + jloc) * BSZ + b];
    }
    for (int idx = tid; idx < JC * BSZ; idx += TPB) {
        const int jl = idx >> 7, b = idx & 127;
        temb_s[idx] = g_temb[(j0 + jl) * BSZ + b];
    }
    const float whv = Wh[j0 + gdt];
    __syncthreads();
    float wfl[4];
    {
        float4 w = *(const float4*)(Wt + 1056 * GD + gdt * 4);
        wfl[0] = w.x; wfl[1] = w.y; wfl[2] = w.z; wfl[3] = w.w;
    }

    float c_[4] = {0.f, 0.f, 0.f, 0.f};

    for (int t = 0; t < TSEQ; ++t) {
        const float* hsrc = g_h[t & 1];
        const float* xsrc = g_xT + t * 64 * BSZ;
        const float4 flv = __ldcg((const float4*)(xsrc + 32 * BSZ + b0k));

        ull acc[4][4];
        #pragma unroll
        for (int g = 0; g < 4; ++g)
            #pragma unroll
            for (int e = 0; e < 4; ++e) acc[g][e] = 0ull;

        float4 p0, p1, p2, p3;
        {
            const float4* s4 = (const float4*)hsrc + tid;
            p0 = __ldcg(s4); p1 = __ldcg(s4 + 256); p2 = __ldcg(s4 + 512); p3 = __ldcg(s4 + 768);
        }

        for (int c = 0; c < NCH; ++c) {
            float4* hb4 = (float4*)(Hs + (c & 1) * 4096);
            hb4[tid] = p0; hb4[tid + 256] = p1; hb4[tid + 512] = p2; hb4[tid + 768] = p3;
            __syncthreads();
            if (c + 1 < NCH) {
                const float* base = (c + 1 < 32) ? (hsrc + (c + 1) * 4096) : xsrc;
                const float4* s4 = (const float4*)base + tid;
                p0 = __ldcg(s4); p1 = __ldcg(s4 + 256); p2 = __ldcg(s4 + 512); p3 = __ldcg(s4 + 768);
            }
            const float* hrow = Hs + (c & 1) * 4096 + kz * 16 * BSZ + b0;
            const float* wrow = Wt + (c * 32 + kz * 16) * GD + gdt * 4;
            #pragma unroll
            for (int i = 0; i < 16; ++i) {
                const ulonglong2 hA = *(const ulonglong2*)(hrow + i * BSZ);
                const ulonglong2 hB = *(const ulonglong2*)(hrow + i * BSZ + 4);
                const float4 wv = *(const float4*)(wrow + i * GD);
                const ull w0 = pk2(wv.x), w1 = pk2(wv.y), w2 = pk2(wv.z), w3 = pk2(wv.w);
                acc[0][0] = f2fma(w0, hA.x, acc[0][0]); acc[0][1] = f2fma(w0, hA.y, acc[0][1]);
                acc[0][2] = f2fma(w0, hB.x, acc[0][2]); acc[0][3] = f2fma(w0, hB.y, acc[0][3]);
                acc[1][0] = f2fma(w1, hA.x, acc[1][0]); acc[1][1] = f2fma(w1, hA.y, acc[1][1]);
                acc[1][2] = f2fma(w1, hB.x, acc[1][2]); acc[1][3] = f2fma(w1, hB.y, acc[1][3]);
                acc[2][0] = f2fma(w2, hA.x, acc[2][0]); acc[2][1] = f2fma(w2, hA.y, acc[2][1]);
                acc[2][2] = f2fma(w2, hB.x, acc[2][2]); acc[2][3] = f2fma(w2, hB.y, acc[2][3]);
                acc[3][0] = f2fma(w3, hA.x, acc[3][0]); acc[3][1] = f2fma(w3, hA.y, acc[3][1]);
                acc[3][2] = f2fma(w3, hB.x, acc[3][2]); acc[3][3] = f2fma(w3, hB.y, acc[3][3]);
            }
        }

        // --- split-K exchange: each half forwards the other's batch partials ---
        float* myred = red + (tid & 127) * 33;
        #pragma unroll
        for (int g = 0; g < 4; ++g)
            #pragma unroll
            for (int e2 = 0; e2 < 2; ++e2) {
                const int e = kz ? e2 : (2 + e2);
                float lo, hi; upk(acc[g][e], lo, hi);
                myred[(1 - kz) * 16 + g * 4 + e2 * 2]     = lo;
                myred[(1 - kz) * 16 + g * 4 + e2 * 2 + 1] = hi;
            }
        __syncthreads();

        float gv[4][4];
        #pragma unroll
        for (int g = 0; g < 4; ++g) {
            #pragma unroll
            for (int e2 = 0; e2 < 2; ++e2) {
                const int e = kz ? (2 + e2) : e2;
                float lo, hi; upk(acc[g][e], lo, hi);
                gv[g][e2 * 2]     = lo + myred[kz * 16 + g * 4 + e2 * 2];
                gv[g][e2 * 2 + 1] = hi + myred[kz * 16 + g * 4 + e2 * 2 + 1];
            }
            const float4 bsv = *(const float4*)(bias_s + (gdt * 4 + g) * BSZ + b0k);
            gv[g][0] += bsv.x + wfl[g] * flv.x;
            gv[g][1] += bsv.y + wfl[g] * flv.y;
            gv[g][2] += bsv.z + wfl[g] * flv.z;
            gv[g][3] += bsv.w + wfl[g] * flv.w;
        }

        float hw4[4];
        #pragma unroll
        for (int j = 0; j < 4; ++j) {
            const float iv = sigm(gv[0][j]);
            const float fv = sigm(gv[1][j]);
            const float gg = tanhf(gv[2][j]);
            const float ov = sigm(gv[3][j]);
            c_[j] = fv * c_[j] + iv * gg;
            float hn = ov * tanhf(c_[j]);
            if (t == 363) {
                const float te = temb_s[gdt * BSZ + b0k + j];
                hn += te; c_[j] += te;
            }
            hw4[j] = hn;
        }
        *(float4*)(g_h[(t + 1) & 1] + (j0 + gdt) * BSZ + b0k) =
            make_float4(hw4[0], hw4[1], hw4[2], hw4[3]);

        if (t >= 364) {
            *(float4*)(red2 + gdt * 132 + b0k) =
                make_float4(hw4[0] * whv, hw4[1] * whv, hw4[2] * whv, hw4[3] * whv);
            __syncthreads();
            if (tid < BSZ) {
                float s = 0.f;
                #pragma unroll
                for (int jl = 0; jl < JC; ++jl) s += red2[jl * 132 + tid];
                g_part[(cta * HHOR + (t - 364)) * BSZ + tid] = s;
            }
        }

        __threadfence();
        __syncthreads();
        if (tid == 0) {
            atomicAdd(&g_cnt, 1u);
            const unsigned target = (unsigned)(t + 1) * NCTA;
            while (*((volatile unsigned*)&g_cnt) < target) { __nanosleep(32); }
            __threadfence();
        }
        __syncthreads();
    }
}

__global__ void out_kernel(const float* __restrict__ bh, float* __restrict__ out)
{
    const int idx = blockIdx.x * blockDim.x + threadIdx.x;
    if (idx >= BSZ * HHOR) return;
    const int b = idx >> 3, tf = idx & 7;
    float s = bh[0];
    #pragma unroll 4
    for (int c = 0; c < NCTA; ++c)
        s += g_part[(c * HHOR + tf) * BSZ + b];
    out[idx] = s;
}

extern "C" void kernel_launch(void* const* d_in, const int* in_sizes, int n_in,
                              void* d_out, int out_size)
{
    cudaFuncSetAttribute(lstm_main, cudaFuncAttributeMaxDynamicSharedMemorySize, SMEMB);
    s_emb_hm<<<128, 256>>>((const float*)d_in[2], (const float*)d_in[9],
                           (const float*)d_in[10], (const float*)d_in[11],
                           (const float*)d_in[12]);
    s_temb<<<128, 128>>>((const float*)d_in[13], (const float*)d_in[14]);
    s_bias<<<32, 256>>>((const float*)d_in[4], (const float*)d_in[5],
                        (const float*)d_in[7], (const float*)d_in[8]);
    s_xT<<<372, 128>>>((const float*)d_in[0], (const float*)d_in[3],
                       (const float*)d_in[1]);
    lstm_main<<<NCTA, TPB, SMEMB>>>((const float*)d_in[6], (const float*)d_in[5],
                                    (const float*)d_in[15]);
    out_kernel<<<(BSZ * HHOR + TPB - 1) / TPB, TPB>>>((const float*)d_in[16], (float*)d_out);
}

// round 6
// speedup vs baseline: 2.3978x; 2.3978x over previous
#include <cuda_runtime.h>
#include <cstdint>

#define BSZ   128
#define HID   1024
#define TSEQ  372
#define NCTA  128
#define TPB   256
#define NKT   136
#define WF_FLOATS (NKT * 4 * 32 * 2)   // 34816 floats per CTA slice

__device__ float    g_hf[2][BSZ * HID];        // fragment-ordered h (fp32)
__device__ float    g_xf[TSEQ * 8 * 8 * 128];  // fragment-ordered x (fp32)
__device__ float    g_wlo[NCTA * WF_FLOATS];   // B_lo fragments per CTA
__device__ float    g_bias[4096 * BSZ];
__device__ float    g_temb[HID * BSZ];
__device__ float    g_hm[512 * BSZ];
__device__ float    g_part[NCTA * 8 * BSZ];
__device__ unsigned g_cnt;

__device__ __forceinline__ float sigm(float x) { return 1.f / (1.f + expf(-x)); }
__device__ __forceinline__ uint32_t tf32u(float x) {
    uint32_t y; asm("cvt.rn.tf32.f32 %0, %1;" : "=r"(y) : "f"(x));
    return y;
}
__device__ __forceinline__ void mma1688(float& d0, float& d1, float& d2, float& d3,
                                        uint32_t a0, uint32_t a1, uint32_t a2, uint32_t a3,
                                        uint32_t b0, uint32_t b1) {
    asm("mma.sync.aligned.m16n8k8.row.col.f32.tf32.tf32.f32 "
        "{%0,%1,%2,%3}, {%4,%5,%6,%7}, {%8,%9}, {%0,%1,%2,%3};"
        : "+f"(d0), "+f"(d1), "+f"(d2), "+f"(d3)
        : "r"(a0), "r"(a1), "r"(a2), "r"(a3), "r"(b0), "r"(b1));
}

// ---------------- setup ----------------
__global__ void s_emb_hm(const float* __restrict__ tval, const float* __restrict__ freqs,
                         const float* __restrict__ phases, const float* __restrict__ W1,
                         const float* __restrict__ b1)
{
    __shared__ float emb[256];
    const int b = blockIdx.x, tid = threadIdx.x;
    const float tv = tval[b];
    emb[tid] = cosf(fmaf(tv, freqs[tid], phases[tid])) * 1.41421356237309515f;
    __syncthreads();
    const float4* e4 = (const float4*)emb;
    for (int u = tid; u < 512; u += 256) {
        const float4* w4 = (const float4*)(W1 + u * 256);
        float s = b1[u];
        #pragma unroll 8
        for (int q = 0; q < 64; ++q) {
            float4 w = w4[q], e = e4[q];
            s += w.x * e.x + w.y * e.y + w.z * e.z + w.w * e.w;
        }
        g_hm[u * BSZ + b] = s * sigm(s);
    }
}

__global__ void s_temb(const float* __restrict__ W2, const float* __restrict__ b2)
{
    __shared__ float sW2[8 * 512];
    const int blk = blockIdx.x, tid = threadIdx.x;
    const int h0 = blk * 8;
    for (int idx = tid; idx < 4096; idx += 128) sW2[idx] = W2[h0 * 512 + idx];
    __syncthreads();
    const int b = tid;
    float acc[8];
    #pragma unroll
    for (int r = 0; r < 8; ++r) acc[r] = b2[h0 + r];
    #pragma unroll 8
    for (int u = 0; u < 512; ++u) {
        const float hmv = g_hm[u * BSZ + b];
        #pragma unroll
        for (int r = 0; r < 8; ++r) acc[r] = fmaf(sW2[r * 512 + u], hmv, acc[r]);
    }
    #pragma unroll
    for (int r = 0; r < 8; ++r) g_temb[(h0 + r) * BSZ + b] = acc[r];
}

__global__ void s_bias(const float* __restrict__ static_attr, const float* __restrict__ W_ih,
                       const float* __restrict__ b_ih, const float* __restrict__ b_hh)
{
    __shared__ float sst[27 * 128];
    __shared__ float sw[128 * 27];
    const int blk = blockIdx.x, tid = threadIdx.x;
    const int r0 = blk * 128;
    for (int idx = tid; idx < 27 * 128; idx += 256) {
        const int k = idx >> 7, b = idx & 127;
        sst[idx] = static_attr[b * 27 + k];
    }
    for (int idx = tid; idx < 128 * 27; idx += 256) {
        const int rl = idx / 27, k = idx - rl * 27;
        sw[idx] = W_ih[(r0 + rl) * 60 + 33 + k];
    }
    __syncthreads();
    for (int o = tid; o < 128 * 128; o += 256) {
        const int rl = o >> 7, b = o & 127;
        const int r = r0 + rl;
        float s = b_ih[r] + b_hh[r];
        #pragma unroll
        for (int k = 0; k < 27; ++k) s = fmaf(sw[rl * 27 + k], sst[k * 128 + b], s);
        g_bias[r * BSZ + b] = s;
    }
    for (int i = tid; i < 4096; i += 256) g_hf[0][blk * 4096 + i] = 0.f;
    if (blk == 0 && tid == 0) g_cnt = 0u;
}

// x in A-fragment order (fp32, no truncation)
__global__ void s_xfrag(const float* __restrict__ x_past, const float* __restrict__ x_future,
                        const float* __restrict__ noisy)
{
    const int t = blockIdx.x, b = threadIdx.x;
    const int mt = b >> 4, g = b & 15;
    const float* src = (t < 365) ? (x_past + (b * 365 + t) * 32)
                                 : (x_future + (b * 7 + (t - 365)) * 32);
    float xv[64];
    const float4* s4 = (const float4*)src;
    #pragma unroll
    for (int q = 0; q < 8; ++q) {
        float4 v = s4[q];
        xv[q * 4 + 0] = v.x; xv[q * 4 + 1] = v.y;
        xv[q * 4 + 2] = v.z; xv[q * 4 + 3] = v.w;
    }
    #pragma unroll
    for (int m = 33; m < 64; ++m) xv[m] = 0.f;
    xv[32] = (t >= 364) ? noisy[b * 8 + (t - 364)] : 0.f;

    float* base = g_xf + t * 8192;
    #pragma unroll
    for (int j = 0; j < 64; ++j) {
        const int kt = j >> 3, jr = j & 7;
        const int lane2 = (g & 7) * 4 + (jr & 3);
        const int slot = (g < 8) ? ((jr < 4) ? 0 : 2) : ((jr < 4) ? 1 : 3);
        base[(kt * 8 + mt) * 128 + lane2 * 4 + slot] = xv[j];
    }
}

// B_lo fragment table (per main-CTA slice)
__global__ void s_wlo(const float* __restrict__ W_hh, const float* __restrict__ W_ih)
{
    const int cta = blockIdx.x, tid = threadIdx.x;
    const int j0 = cta * 8;
    float* dst = g_wlo + cta * WF_FLOATS;
    for (int idx = tid; idx < WF_FLOATS; idx += 256) {
        const int half = idx & 1, pos = idx >> 1;
        const int ln = pos & 31, nt = (pos >> 5) & 3, kt = pos >> 7;
        const int n = nt * 8 + (ln >> 2);
        const int k = kt * 8 + (ln & 3) + half * 4;
        const int r = (n >> 3) * HID + j0 + (n & 7);
        float v = (k < 1024) ? W_hh[r * 1024 + k]
                             : ((k < 1057) ? W_ih[r * 60 + (k - 1024)] : 0.f);
        const float hi = __uint_as_float(tf32u(v));
        dst[idx] = __uint_as_float(tf32u(v - hi));
    }
}

// ---------------- main LSTM (3xTF32 mma.sync) ----------------
__global__ void __launch_bounds__(TPB, 1)
lstm_main(const float* __restrict__ W_hh, const float* __restrict__ W_ih,
          const float* __restrict__ Wh)
{
    extern __shared__ float sm[];
    float* Wf     = sm;                    // B_hi frags
    float* bias_s = Wf + WF_FLOATS;
    float* temb_s = bias_s + 4096;
    float* wh_s   = temb_s + 1024;

    const int tid = threadIdx.x;
    const int w   = tid >> 5, lane = tid & 31;
    const int g   = lane >> 2, tig = lane & 3;
    const int cta = blockIdx.x;
    const int j0  = cta * 8;

    for (int idx = tid; idx < WF_FLOATS; idx += TPB) {
        const int half = idx & 1, pos = idx >> 1;
        const int ln = pos & 31, nt = (pos >> 5) & 3, kt = pos >> 7;
        const int n = nt * 8 + (ln >> 2);
        const int k = kt * 8 + (ln & 3) + half * 4;
        const int r = (n >> 3) * HID + j0 + (n & 7);
        float v = (k < 1024) ? W_hh[r * 1024 + k]
                             : ((k < 1057) ? W_ih[r * 60 + (k - 1024)] : 0.f);
        Wf[idx] = __uint_as_float(tf32u(v));
    }
    for (int idx = tid; idx < 32 * 128; idx += TPB) {
        const int n = idx >> 7, b = idx & 127;
        bias_s[idx] = g_bias[((n >> 3) * HID + j0 + (n & 7)) * BSZ + b];
    }
    for (int idx = tid; idx < 8 * 128; idx += TPB) {
        const int jl = idx >> 7, b = idx & 127;
        temb_s[idx] = g_temb[(j0 + jl) * BSZ + b];
    }
    if (tid < 8) wh_s[tid] = Wh[j0 + tid];
    __syncthreads();

    const float* wlo = g_wlo + cta * WF_FLOATS;
    const int b_lo = w * 16 + g, b_hi = b_lo + 8;
    const int jl0 = 2 * tig, jl1 = jl0 + 1;
    float cst[4] = {0.f, 0.f, 0.f, 0.f};

    for (int t = 0; t < TSEQ; ++t) {
        const float4* hb = (const float4*)(g_hf[t & 1]);
        const float4* xb = (const float4*)(g_xf + t * 8192);

        float acc[4][4];
        #pragma unroll
        for (int nt = 0; nt < 4; ++nt)
            #pragma unroll
            for (int e = 0; e < 4; ++e) acc[nt][e] = 0.f;

        float4 ring[8];
        #pragma unroll
        for (int kk = 0; kk < 8; ++kk)
            ring[kk] = __ldcg(hb + kk * 256 + w * 32 + lane);

        #pragma unroll 1
        for (int c = 0; c < 17; ++c) {
            const float4* nxt = (c < 15) ? (hb + (c + 1) * 2048) : xb;
            #pragma unroll
            for (int kk = 0; kk < 8; ++kk) {
                const float4 a = ring[kk];
                if (c < 16) ring[kk] = __ldcg(nxt + kk * 256 + w * 32 + lane);
                const uint32_t h0 = tf32u(a.x), h1 = tf32u(a.y);
                const uint32_t h2 = tf32u(a.z), h3 = tf32u(a.w);
                const uint32_t l0 = tf32u(a.x - __uint_as_float(h0));
                const uint32_t l1 = tf32u(a.y - __uint_as_float(h1));
                const uint32_t l2 = tf32u(a.z - __uint_as_float(h2));
                const uint32_t l3 = tf32u(a.w - __uint_as_float(h3));
                const int kt = c * 8 + kk;
                #pragma unroll
                for (int nt = 0; nt < 4; ++nt) {
                    const int fo = ((kt * 4 + nt) * 32 + lane) * 2;
                    const float2 bh = *(const float2*)(Wf + fo);
                    const float2 bl = __ldcg((const float2*)(wlo + fo));
                    const uint32_t bh0 = __float_as_uint(bh.x), bh1 = __float_as_uint(bh.y);
                    mma1688(acc[nt][0], acc[nt][1], acc[nt][2], acc[nt][3],
                            h0, h1, h2, h3, bh0, bh1);
                    mma1688(acc[nt][0], acc[nt][1], acc[nt][2], acc[nt][3],
                            l0, l1, l2, l3, bh0, bh1);
                    mma1688(acc[nt][0], acc[nt][1], acc[nt][2], acc[nt][3],
                            h0, h1, h2, h3,
                            __float_as_uint(bl.x), __float_as_uint(bl.y));
                }
            }
        }

        float hv[4];
        float* hnext = g_hf[(t + 1) & 1] + cta * 1024 + w * 128;
        #pragma unroll
        for (int e = 0; e < 4; ++e) {
            const int b  = (e < 2) ? b_lo : b_hi;
            const int jl = (e & 1) ? jl1 : jl0;
            const float gi = acc[0][e] + bias_s[(0 + jl) * 128 + b];
            const float gf = acc[1][e] + bias_s[(8 + jl) * 128 + b];
            const float gg = acc[2][e] + bias_s[(16 + jl) * 128 + b];
            const float go = acc[3][e] + bias_s[(24 + jl) * 128 + b];
            cst[e] = sigm(gf) * cst[e] + sigm(gi) * tanhf(gg);
            float hn = sigm(go) * tanhf(cst[e]);
            if (t == 363) {
                const float te = temb_s[jl * 128 + b];
                hn += te; cst[e] += te;
            }
            hv[e] = hn;
            const int lane2 = g * 4 + (jl & 3);
            const int slot  = (e < 2) ? ((jl < 4) ? 0 : 2) : ((jl < 4) ? 1 : 3);
            hnext[lane2 * 4 + slot] = hn;
        }

        if (t >= 364) {
            float p = hv[0] * wh_s[jl0] + hv[1] * wh_s[jl1];
            float q = hv[2] * wh_s[jl0] + hv[3] * wh_s[jl1];
            p += __shfl_xor_sync(0xFFFFFFFFu, p, 1);
            p += __shfl_xor_sync(0xFFFFFFFFu, p, 2);
            q += __shfl_xor_sync(0xFFFFFFFFu, q, 1);
            q += __shfl_xor_sync(0xFFFFFFFFu, q, 2);
            if (tig == 0) {
                g_part[(cta * 8 + (t - 364)) * BSZ + b_lo] = p;
                g_part[(cta * 8 + (t - 364)) * BSZ + b_hi] = q;
            }
        }

        __threadfence();
        __syncthreads();
        if (tid == 0) {
            atomicAdd(&g_cnt, 1u);
            const unsigned target = (unsigned)(t + 1) * NCTA;
            while (*((volatile unsigned*)&g_cnt) < target) { __nanosleep(32); }
            __threadfence();
        }
        __syncthreads();
    }
}

__global__ void out_kernel(const float* __restrict__ bh, float* __restrict__ out)
{
    const int idx = blockIdx.x * blockDim.x + threadIdx.x;
    if (idx >= BSZ * 8) return;
    const int b = idx >> 3, tf = idx & 7;
    float s = bh[0];
    #pragma unroll 4
    for (int c = 0; c < NCTA; ++c)
        s += g_part[(c * 8 + tf) * BSZ + b];
    out[idx] = s;
}

extern "C" void kernel_launch(void* const* d_in, const int* in_sizes, int n_in,
                              void* d_out, int out_size)
{
    const int smemb = (WF_FLOATS + 4096 + 1024 + 8) * 4;
    cudaFuncSetAttribute(lstm_main, cudaFuncAttributeMaxDynamicSharedMemorySize, smemb);
    s_emb_hm<<<128, 256>>>((const float*)d_in[2], (const float*)d_in[9],
                           (const float*)d_in[10], (const float*)d_in[11],
                           (const float*)d_in[12]);
    s_temb<<<128, 128>>>((const float*)d_in[13], (const float*)d_in[14]);
    s_bias<<<32, 256>>>((const float*)d_in[4], (const float*)d_in[5],
                        (const float*)d_in[7], (const float*)d_in[8]);
    s_xfrag<<<372, 128>>>((const float*)d_in[0], (const float*)d_in[3],
                          (const float*)d_in[1]);
    s_wlo<<<NCTA, 256>>>((const float*)d_in[6], (const float*)d_in[5]);
    lstm_main<<<NCTA, TPB, smemb>>>((const float*)d_in[6], (const float*)d_in[5],
                                    (const float*)d_in[15]);
    out_kernel<<<(BSZ * 8 + TPB - 1) / TPB, TPB>>>((const float*)d_in[16], (float*)d_out);
}

// round 7
// speedup vs baseline: 3.4348x; 1.4325x over previous
#include <cuda_runtime.h>
#include <cuda_fp16.h>
#include <cstdint>

#define BSZ   128
#define HID   1024
#define TSEQ  372
#define NCTA  128
#define TPB   256
#define NKT16 68
#define SB_U32 (NKT16 * 4 * 32 * 4)     // 34816 u32 = 139264 B

__device__ uint32_t g_hh[2][65536];      // h hi fragments (fp16x2)
__device__ uint32_t g_hl[2][65536];      // h lo*2048 fragments
__device__ uint32_t g_xh[TSEQ * 4096];   // x hi fragments
__device__ uint32_t g_xl[TSEQ * 4096];   // x lo*2048 fragments
__device__ float    g_bias[4096 * BSZ];
__device__ float    g_temb[HID * BSZ];
__device__ float    g_hm[512 * BSZ];
__device__ float    g_part[NCTA * 8 * BSZ];
__device__ unsigned g_cnt;

__device__ __forceinline__ float sigm(float x) { return 1.f / (1.f + expf(-x)); }

// pack two f32 -> f16x2, loE in LOW half
__device__ __forceinline__ uint32_t pk_h2(float loE, float hiE) {
    uint32_t r;
    asm("cvt.rn.f16x2.f32 %0, %1, %2;" : "=r"(r) : "f"(hiE), "f"(loE));
    return r;
}
// split v (already pre-scaled as desired): hi = f16(v), lo = f16((v-hi)*2048)
__device__ __forceinline__ void split16(float v, float& hi, float& lo) {
    __half h = __float2half_rn(v);
    hi = __half2float(h);
    lo = (v - hi) * 2048.0f;
}
__device__ __forceinline__ void mma16816(float& d0, float& d1, float& d2, float& d3,
                                         uint32_t a0, uint32_t a1, uint32_t a2, uint32_t a3,
                                         uint32_t b0, uint32_t b1) {
    asm("mma.sync.aligned.m16n8k16.row.col.f32.f16.f16.f32 "
        "{%0,%1,%2,%3}, {%4,%5,%6,%7}, {%8,%9}, {%0,%1,%2,%3};"
        : "+f"(d0), "+f"(d1), "+f"(d2), "+f"(d3)
        : "r"(a0), "r"(a1), "r"(a2), "r"(a3), "r"(b0), "r"(b1));
}

// ---------------- setup ----------------
__global__ void s_emb_hm(const float* __restrict__ tval, const float* __restrict__ freqs,
                         const float* __restrict__ phases, const float* __restrict__ W1,
                         const float* __restrict__ b1)
{
    __shared__ float emb[256];
    const int b = blockIdx.x, tid = threadIdx.x;
    const float tv = tval[b];
    emb[tid] = cosf(fmaf(tv, freqs[tid], phases[tid])) * 1.41421356237309515f;
    __syncthreads();
    const float4* e4 = (const float4*)emb;
    for (int u = tid; u < 512; u += 256) {
        const float4* w4 = (const float4*)(W1 + u * 256);
        float s = b1[u];
        #pragma unroll 8
        for (int q = 0; q < 64; ++q) {
            float4 w = w4[q], e = e4[q];
            s += w.x * e.x + w.y * e.y + w.z * e.z + w.w * e.w;
        }
        g_hm[u * BSZ + b] = s * sigm(s);
    }
}

__global__ void s_temb(const float* __restrict__ W2, const float* __restrict__ b2)
{
    __shared__ float sW2[8 * 512];
    const int blk = blockIdx.x, tid = threadIdx.x;
    const int h0 = blk * 8;
    for (int idx = tid; idx < 4096; idx += 128) sW2[idx] = W2[h0 * 512 + idx];
    __syncthreads();
    const int b = tid;
    float acc[8];
    #pragma unroll
    for (int r = 0; r < 8; ++r) acc[r] = b2[h0 + r];
    #pragma unroll 8
    for (int u = 0; u < 512; ++u) {
        const float hmv = g_hm[u * BSZ + b];
        #pragma unroll
        for (int r = 0; r < 8; ++r) acc[r] = fmaf(sW2[r * 512 + u], hmv, acc[r]);
    }
    #pragma unroll
    for (int r = 0; r < 8; ++r) g_temb[(h0 + r) * BSZ + b] = acc[r];
}

__global__ void s_bias(const float* __restrict__ static_attr, const float* __restrict__ W_ih,
                       const float* __restrict__ b_ih, const float* __restrict__ b_hh)
{
    __shared__ float sst[27 * 128];
    __shared__ float sw[128 * 27];
    const int blk = blockIdx.x, tid = threadIdx.x;
    const int r0 = blk * 128;
    for (int idx = tid; idx < 27 * 128; idx += 256) {
        const int k = idx >> 7, b = idx & 127;
        sst[idx] = static_attr[b * 27 + k];
    }
    for (int idx = tid; idx < 128 * 27; idx += 256) {
        const int rl = idx / 27, k = idx - rl * 27;
        sw[idx] = W_ih[(r0 + rl) * 60 + 33 + k];
    }
    __syncthreads();
    for (int o = tid; o < 128 * 128; o += 256) {
        const int rl = o >> 7, b = o & 127;
        const int r = r0 + rl;
        float s = b_ih[r] + b_hh[r];
        #pragma unroll
        for (int k = 0; k < 27; ++k) s = fmaf(sw[rl * 27 + k], sst[k * 128 + b], s);
        g_bias[r * BSZ + b] = s;
    }
    for (int i = tid; i < 2048; i += 256) {
        g_hh[0][blk * 2048 + i] = 0u;
        g_hl[0][blk * 2048 + i] = 0u;
    }
    if (blk == 0 && tid == 0) g_cnt = 0u;
}

// x into fp16-split A-fragment layout
__global__ void s_xfrag(const float* __restrict__ x_past, const float* __restrict__ x_future,
                        const float* __restrict__ noisy)
{
    const int t = blockIdx.x, b = threadIdx.x;
    const int mt = b >> 4, r = b & 15;
    const int gp = r & 7, up = r >> 3;
    const float* src = (t < 365) ? (x_past + (b * 365 + t) * 32)
                                 : (x_future + (b * 7 + (t - 365)) * 32);
    float xv[64];
    const float4* s4 = (const float4*)src;
    #pragma unroll
    for (int q = 0; q < 8; ++q) {
        float4 v = s4[q];
        xv[q * 4 + 0] = v.x; xv[q * 4 + 1] = v.y;
        xv[q * 4 + 2] = v.z; xv[q * 4 + 3] = v.w;
    }
    #pragma unroll
    for (int m = 33; m < 64; ++m) xv[m] = 0.f;
    xv[32] = (t >= 364) ? noisy[b * 8 + (t - 364)] : 0.f;

    uint32_t* xh = g_xh + t * 4096;
    uint32_t* xl = g_xl + t * 4096;
    #pragma unroll
    for (int kt = 0; kt < 4; ++kt) {
        #pragma unroll
        for (int tg = 0; tg < 4; ++tg) {
            const int base = ((kt * 8 + mt) * 32 + gp * 4 + tg) * 4;
            #pragma unroll
            for (int hk = 0; hk < 2; ++hk) {   // low-k pair / high-k pair
                const int k0 = kt * 16 + tg * 2 + hk * 8;
                float h0, l0, h1, l1;
                split16(xv[k0], h0, l0);
                split16(xv[k0 + 1], h1, l1);
                xh[base + up + hk * 2] = pk_h2(h0, h1);
                xl[base + up + hk * 2] = pk_h2(l0, l1);
            }
        }
    }
}

// ---------------- main LSTM (fp16-split mma.sync) ----------------
__global__ void __launch_bounds__(TPB, 1)
lstm_main(const float* __restrict__ W_hh, const float* __restrict__ W_ih,
          const float* __restrict__ Wh)
{
    extern __shared__ __align__(16) uint32_t sm[];
    uint32_t* sB   = sm;                      // [68][4][32][4] u32
    float* bias_s  = (float*)(sm + SB_U32);
    float* temb_s  = bias_s + 4096;
    float* wh_s    = temb_s + 1024;

    const int tid = threadIdx.x;
    const int w   = tid >> 5, lane = tid & 31;
    const int g   = lane >> 2, tig = lane & 3;
    const int cta = blockIdx.x;
    const int j0  = cta * 8;

    // weights: split fp16 B fragments (hi and lo interleaved for one LDS.128)
    for (int idx = tid; idx < NKT16 * 4 * 32; idx += TPB) {
        const int ln = idx & 31, nt = (idx >> 5) & 3, kt = idx >> 7;
        const int n = nt * 8 + (ln >> 2);
        const int tg = ln & 3;
        const int r = (n >> 3) * HID + j0 + (n & 7);
        const int k0 = kt * 16 + tg * 2;
        float wv[4];
        #pragma unroll
        for (int q = 0; q < 4; ++q) {
            const int k = k0 + (q >> 1) * 8 + (q & 1);
            float v = (k < 1024) ? W_hh[r * 1024 + k]
                                 : ((k < 1057) ? W_ih[r * 60 + (k - 1024)] : 0.f);
            wv[q] = v * 256.0f;
        }
        float h0, l0, h1, l1, h2, l2, h3, l3;
        split16(wv[0], h0, l0); split16(wv[1], h1, l1);
        split16(wv[2], h2, l2); split16(wv[3], h3, l3);
        uint32_t* dst = sB + idx * 4;
        dst[0] = pk_h2(h0, h1);   // b_hi, k pair low
        dst[1] = pk_h2(h2, h3);   // b_hi, k pair high
        dst[2] = pk_h2(l0, l1);   // b_lo
        dst[3] = pk_h2(l2, l3);
    }
    for (int idx = tid; idx < 32 * 128; idx += TPB) {
        const int n = idx >> 7, b = idx & 127;
        bias_s[idx] = g_bias[((n >> 3) * HID + j0 + (n & 7)) * BSZ + b];
    }
    for (int idx = tid; idx < 8 * 128; idx += TPB) {
        const int jl = idx >> 7, b = idx & 127;
        temb_s[idx] = g_temb[(j0 + jl) * BSZ + b];
    }
    if (tid < 8) wh_s[tid] = Wh[j0 + tid];
    __syncthreads();

    const int b_lo = w * 16 + g, b_hi = b_lo + 8;
    const int jl0 = 2 * tig, jl1 = jl0 + 1;
    const int ktw = cta >> 1;                 // ktile this CTA's h lands in
    const int regw = (cta & 1) * 2;
    float cst[4] = {0.f, 0.f, 0.f, 0.f};

    const uint4* sB4 = (const uint4*)sB;

    for (int t = 0; t < TSEQ; ++t) {
        const uint4* hh4 = (const uint4*)(g_hh[t & 1]);
        const uint4* hl4 = (const uint4*)(g_hl[t & 1]);
        const uint4* xh4 = (const uint4*)(g_xh + t * 4096);
        const uint4* xl4 = (const uint4*)(g_xl + t * 4096);

        float accM[4][4], accC[4][4];
        #pragma unroll
        for (int nt = 0; nt < 4; ++nt)
            #pragma unroll
            for (int e = 0; e < 4; ++e) { accM[nt][e] = 0.f; accC[nt][e] = 0.f; }

        uint4 rh[4], rl[4];
        #pragma unroll
        for (int p = 0; p < 4; ++p) {
            const int off = (p * 8 + w) * 32 + lane;
            rh[p] = __ldcg(hh4 + off);
            rl[p] = __ldcg(hl4 + off);
        }

        #pragma unroll 4
        for (int kt = 0; kt < NKT16; ++kt) {
            const int cur = kt & 3;
            const uint4 Ah = rh[cur], Al = rl[cur];
            uint4 Bv[4];
            #pragma unroll
            for (int nt = 0; nt < 4; ++nt)
                Bv[nt] = sB4[(kt * 4 + nt) * 32 + lane];
            #pragma unroll
            for (int nt = 0; nt < 4; ++nt)
                mma16816(accM[nt][0], accM[nt][1], accM[nt][2], accM[nt][3],
                         Ah.x, Ah.y, Ah.z, Ah.w, Bv[nt].x, Bv[nt].y);
            #pragma unroll
            for (int nt = 0; nt < 4; ++nt)
                mma16816(accC[nt][0], accC[nt][1], accC[nt][2], accC[nt][3],
                         Al.x, Al.y, Al.z, Al.w, Bv[nt].x, Bv[nt].y);
            #pragma unroll
            for (int nt = 0; nt < 4; ++nt)
                mma16816(accC[nt][0], accC[nt][1], accC[nt][2], accC[nt][3],
                         Ah.x, Ah.y, Ah.z, Ah.w, Bv[nt].z, Bv[nt].w);
            if (kt + 4 < NKT16) {
                const int nk = kt + 4;
                if (nk < 64) {
                    const int off = (nk * 8 + w) * 32 + lane;
                    rh[cur] = __ldcg(hh4 + off);
                    rl[cur] = __ldcg(hl4 + off);
                } else {
                    const int off = ((nk - 64) * 8 + w) * 32 + lane;
                    rh[cur] = __ldcg(xh4 + off);
                    rl[cur] = __ldcg(xl4 + off);
                }
            }
        }

        // epilogue
        float hv[4];
        #pragma unroll
        for (int e = 0; e < 4; ++e) {
            const int b  = (e < 2) ? b_lo : b_hi;
            const int jl = (e & 1) ? jl1 : jl0;
            const float gi = (accM[0][e] + accC[0][e] * 4.8828125e-4f) * 0.00390625f + bias_s[(0 + jl) * 128 + b];
            const float gf = (accM[1][e] + accC[1][e] * 4.8828125e-4f) * 0.00390625f + bias_s[(8 + jl) * 128 + b];
            const float gg = (accM[2][e] + accC[2][e] * 4.8828125e-4f) * 0.00390625f + bias_s[(16 + jl) * 128 + b];
            const float go = (accM[3][e] + accC[3][e] * 4.8828125e-4f) * 0.00390625f + bias_s[(24 + jl) * 128 + b];
            cst[e] = sigm(gf) * cst[e] + sigm(gi) * tanhf(gg);
            float hn = sigm(go) * tanhf(cst[e]);
            if (t == 363) {
                const float te = temb_s[jl * 128 + b];
                hn += te; cst[e] += te;
            }
            hv[e] = hn;
        }

        // store h split into fragment layout for next step
        {
            float h0, l0, h1, l1, h2, l2, h3, l3;
            split16(hv[0], h0, l0); split16(hv[1], h1, l1);
            split16(hv[2], h2, l2); split16(hv[3], h3, l3);
            const int addr = ((ktw * 8 + w) * 32 + g * 4 + tig) * 4 + regw;
            uint2 vh = make_uint2(pk_h2(h0, h1), pk_h2(h2, h3));
            uint2 vl = make_uint2(pk_h2(l0, l1), pk_h2(l2, l3));
            *(uint2*)(&g_hh[(t + 1) & 1][addr]) = vh;
            *(uint2*)(&g_hl[(t + 1) & 1][addr]) = vl;
        }

        if (t >= 364) {
            float p = hv[0] * wh_s[jl0] + hv[1] * wh_s[jl1];
            float q = hv[2] * wh_s[jl0] + hv[3] * wh_s[jl1];
            p += __shfl_xor_sync(0xFFFFFFFFu, p, 1);
            p += __shfl_xor_sync(0xFFFFFFFFu, p, 2);
            q += __shfl_xor_sync(0xFFFFFFFFu, q, 1);
            q += __shfl_xor_sync(0xFFFFFFFFu, q, 2);
            if (tig == 0) {
                g_part[(cta * 8 + (t - 364)) * BSZ + b_lo] = p;
                g_part[(cta * 8 + (t - 364)) * BSZ + b_hi] = q;
            }
        }

        __threadfence();
        __syncthreads();
        if (tid == 0) {
            atomicAdd(&g_cnt, 1u);
            const unsigned target = (unsigned)(t + 1) * NCTA;
            while (*((volatile unsigned*)&g_cnt) < target) { __nanosleep(32); }
            __threadfence();
        }
        __syncthreads();
    }
}

__global__ void out_kernel(const float* __restrict__ bh, float* __restrict__ out)
{
    const int idx = blockIdx.x * blockDim.x + threadIdx.x;
    if (idx >= BSZ * 8) return;
    const int b = idx >> 3, tf = idx & 7;
    float s = bh[0];
    #pragma unroll 4
    for (int c = 0; c < NCTA; ++c)
        s += g_part[(c * 8 + tf) * BSZ + b];
    out[idx] = s;
}

extern "C" void kernel_launch(void* const* d_in, const int* in_sizes, int n_in,
                              void* d_out, int out_size)
{
    const int smemb = SB_U32 * 4 + (4096 + 1024 + 8) * 4;
    cudaFuncSetAttribute(lstm_main, cudaFuncAttributeMaxDynamicSharedMemorySize, smemb);
    s_emb_hm<<<128, 256>>>((const float*)d_in[2], (const float*)d_in[9],
                           (const float*)d_in[10], (const float*)d_in[11],
                           (const float*)d_in[12]);
    s_temb<<<128, 128>>>((const float*)d_in[13], (const float*)d_in[14]);
    s_bias<<<32, 256>>>((const float*)d_in[4], (const float*)d_in[5],
                        (const float*)d_in[7], (const float*)d_in[8]);
    s_xfrag<<<372, 128>>>((const float*)d_in[0], (const float*)d_in[3],
                          (const float*)d_in[1]);
    lstm_main<<<NCTA, TPB, smemb>>>((const float*)d_in[6], (const float*)d_in[5],
                                    (const float*)d_in[15]);
    out_kernel<<<(BSZ * 8 + TPB - 1) / TPB, TPB>>>((const float*)d_in[16], (float*)d_out);
}